// round 3
// baseline (speedup 1.0000x reference)
#include <cuda_runtime.h>
#include <cstdint>

// ---------------------------------------------------------------------------
// img_attn: B=32, Nv=1556, Ni=256, N=1812 tokens, D=512, IMG_D=2048
//
// Pipeline:
//  K0 copy_verts:  verts_f -> g_x[:, :1556, :]
//  G1 gemm:        img_f @ fc_w^T + fc_b    -> g_x[:, 1556:, :]   (row-remap C)
//  G2 gemm:        g_x @ q_w^T + q_b        -> g_q
//  G3 gemm:        g_x @ k_w^T + k_b        -> g_k
//  K4 norm:        l2-normalize g_q/g_k rows; logits a = (q.w_g)*SCALE
//  K5 softmax:     per-batch softmax over 1812 tokens (in-place in g_a)
//  K6 gsum+reduce: g[b,:] = sum_n a_n * q_n   (deterministic split-K partials)
//  K7 ymul:        g_y = g[b] * g_k  (vert rows only)
//  G4 gemm:        g_y @ proj_w^T + proj_b + g_q  -> g_o1   (row-remap E)
//  G5 gemm:        g_o1 @ final_w^T + final_b + verts_f -> d_out
//
// GEMM: 128x128x32 tiles, tf32 mma.sync m16n8k8, cp.async double buffer,
// conflict-free smem (row stride 36 floats), 256 threads, 2 CTAs/SM.
// ---------------------------------------------------------------------------

#define BATCH 32
#define NVERT 1556
#define NIMG  256
#define NTOK  1812
#define DIM   512
#define IMGDIM 2048
#define M_ALL (BATCH * NTOK)    // 57984 (multiple of 128)
#define M_VRT (BATCH * NVERT)   // 49792 (multiple of 128)
#define M_IMG (BATCH * NIMG)    // 8192
#define ATT_SCALE 0.08838834764831845f   // (512/4)^-0.5
#define NSPLIT 16

// scratch (static device allocations; no cudaMalloc anywhere)
__device__ __align__(256) float g_x [(size_t)M_ALL * DIM];
__device__ __align__(256) float g_q [(size_t)M_ALL * DIM];
__device__ __align__(256) float g_k [(size_t)M_ALL * DIM];
__device__ __align__(256) float g_y [(size_t)M_VRT * DIM];
__device__ __align__(256) float g_o1[(size_t)M_VRT * DIM];
__device__ __align__(256) float g_a [M_ALL];
__device__ __align__(256) float g_g [BATCH * DIM];
__device__ __align__(256) float g_gp[NSPLIT * BATCH * DIM];

// ---------------------------------------------------------------------------
// GEMM: C[m,n] = sum_k A[m,k]*B[n,k] + bias[n] (+ E[emap(m), n])
// C row index = cmap(m). All leading dims of C/E are DIM.
// ---------------------------------------------------------------------------

struct RMap { int div, stride, off; };

__device__ __forceinline__ int rmap_apply(const RMap m, int r) {
    int q = r / m.div;
    return q * m.stride + (r - q * m.div) + m.off;
}

__device__ __forceinline__ uint32_t f2tf32(float x) {
    uint32_t r;
    asm("cvt.rna.tf32.f32 %0, %1;" : "=r"(r) : "f"(x));
    return r;
}

__device__ __forceinline__ void mma_tf32(float* d, const uint32_t* a, const uint32_t* b) {
    asm volatile(
        "mma.sync.aligned.m16n8k8.row.col.f32.tf32.tf32.f32 "
        "{%0,%1,%2,%3},{%4,%5,%6,%7},{%8,%9},{%0,%1,%2,%3};"
        : "+f"(d[0]), "+f"(d[1]), "+f"(d[2]), "+f"(d[3])
        : "r"(a[0]), "r"(a[1]), "r"(a[2]), "r"(a[3]), "r"(b[0]), "r"(b[1]));
}

#define BM 128
#define BN 128
#define BKS 32
#define SSTR 36   // BKS + 4: bank-conflict-free (8 rows * 4-bank shift = 32 banks)
#define GEMM_SMEM (2 * (BM + BN) * SSTR * (int)sizeof(float))  // 73728 B

__global__ __launch_bounds__(256, 2)
void gemm_tn_kernel(const float* __restrict__ A, const float* __restrict__ Bw,
                    const float* __restrict__ bias, const float* __restrict__ E,
                    float* __restrict__ C, int K, RMap cmap, RMap emap)
{
    extern __shared__ float smem[];
    float* As = smem;                       // [2][BM][SSTR]
    float* Bs = smem + 2 * BM * SSTR;       // [2][BN][SSTR]

    const int tid  = threadIdx.x;
    const int lane = tid & 31;
    const int warp = tid >> 5;
    const int wm   = warp >> 2;   // 0..1 -> 64 rows each
    const int wn   = warp & 3;    // 0..3 -> 32 cols each
    const long rowA0 = (long)blockIdx.y * BM;
    const long rowB0 = (long)blockIdx.x * BN;

    float acc[4][4][4];
#pragma unroll
    for (int mt = 0; mt < 4; mt++)
#pragma unroll
        for (int nt = 0; nt < 4; nt++)
#pragma unroll
            for (int i = 0; i < 4; i++) acc[mt][nt][i] = 0.f;

    auto load_tiles = [&](int buf, int kt) {
        const int k0 = kt * BKS;
#pragma unroll
        for (int i = 0; i < 4; i++) {
            const int idx = tid + i * 256;          // 0..1023
            const int r = idx >> 3;                 // 0..127
            const int c = (idx & 7) << 2;           // 0,4,...,28
            {
                const float* gp = A + (rowA0 + r) * (long)K + k0 + c;
                uint32_t sp = (uint32_t)__cvta_generic_to_shared(
                    As + buf * BM * SSTR + r * SSTR + c);
                asm volatile("cp.async.cg.shared.global [%0], [%1], 16;"
                             :: "r"(sp), "l"(gp));
            }
            {
                const float* gp = Bw + (rowB0 + r) * (long)K + k0 + c;
                uint32_t sp = (uint32_t)__cvta_generic_to_shared(
                    Bs + buf * BN * SSTR + r * SSTR + c);
                asm volatile("cp.async.cg.shared.global [%0], [%1], 16;"
                             :: "r"(sp), "l"(gp));
            }
        }
        asm volatile("cp.async.commit_group;" ::: "memory");
    };

    const int T = K / BKS;
    load_tiles(0, 0);
    int buf = 0;

    for (int t = 0; t < T; t++) {
        asm volatile("cp.async.wait_group 0;" ::: "memory");
        __syncthreads();
        if (t + 1 < T) load_tiles(buf ^ 1, t + 1);

        const float* Ab = As + buf * BM * SSTR;
        const float* Bb = Bs + buf * BN * SSTR;
#pragma unroll
        for (int ks = 0; ks < 4; ks++) {
            const int kc = ks * 8 + (lane & 3);
            uint32_t af[4][4], bf[4][2];
#pragma unroll
            for (int mt = 0; mt < 4; mt++) {
                const int r = wm * 64 + mt * 16 + (lane >> 2);
                af[mt][0] = f2tf32(Ab[r * SSTR + kc]);
                af[mt][1] = f2tf32(Ab[(r + 8) * SSTR + kc]);
                af[mt][2] = f2tf32(Ab[r * SSTR + kc + 4]);
                af[mt][3] = f2tf32(Ab[(r + 8) * SSTR + kc + 4]);
            }
#pragma unroll
            for (int nt = 0; nt < 4; nt++) {
                const int n = wn * 32 + nt * 8 + (lane >> 2);
                bf[nt][0] = f2tf32(Bb[n * SSTR + kc]);
                bf[nt][1] = f2tf32(Bb[n * SSTR + kc + 4]);
            }
#pragma unroll
            for (int mt = 0; mt < 4; mt++)
#pragma unroll
                for (int nt = 0; nt < 4; nt++)
                    mma_tf32(acc[mt][nt], af[mt], bf[nt]);
        }
        buf ^= 1;
    }

    // epilogue: + bias (+E), write via row maps
#pragma unroll
    for (int mt = 0; mt < 4; mt++) {
        const int gr0 = (int)rowA0 + wm * 64 + mt * 16 + (lane >> 2);
        const int gr1 = gr0 + 8;
        const int cr0 = rmap_apply(cmap, gr0);
        const int cr1 = rmap_apply(cmap, gr1);
        int er0 = 0, er1 = 0;
        if (E) { er0 = rmap_apply(emap, gr0); er1 = rmap_apply(emap, gr1); }
#pragma unroll
        for (int nt = 0; nt < 4; nt++) {
            const int gc = (int)rowB0 + wn * 32 + nt * 8 + ((lane & 3) << 1);
            const float2 bb = *(const float2*)(bias + gc);
            float2 v0 = make_float2(acc[mt][nt][0] + bb.x, acc[mt][nt][1] + bb.y);
            float2 v1 = make_float2(acc[mt][nt][2] + bb.x, acc[mt][nt][3] + bb.y);
            if (E) {
                const float2 e0 = *(const float2*)(E + (size_t)er0 * DIM + gc);
                const float2 e1 = *(const float2*)(E + (size_t)er1 * DIM + gc);
                v0.x += e0.x; v0.y += e0.y;
                v1.x += e1.x; v1.y += e1.y;
            }
            *(float2*)(C + (size_t)cr0 * DIM + gc) = v0;
            *(float2*)(C + (size_t)cr1 * DIM + gc) = v1;
        }
    }
}

// ---------------------------------------------------------------------------
// Elementwise / reduction kernels
// ---------------------------------------------------------------------------

__global__ __launch_bounds__(256)
void copy_verts_kernel(const float4* __restrict__ v) {
    const int idx = blockIdx.x * 256 + threadIdx.x;   // < M_VRT*128 (exact)
    const int m = idx >> 7, j = idx & 127;
    const int b = m / NVERT, t = m - b * NVERT;
    ((float4*)g_x)[((size_t)(b * NTOK + t)) * 128 + j] = v[idx];
}

// blockIdx.y==0 -> normalize g_q rows + logits; ==1 -> normalize g_k rows
__global__ __launch_bounds__(128)
void norm_kernel(const float* __restrict__ wg) {
    const int row = blockIdx.x;
    float* buf = (blockIdx.y == 0) ? g_q : g_k;
    const int tid = threadIdx.x;
    float4* rp = (float4*)(buf + (size_t)row * DIM);
    float4 v = rp[tid];
    float ss = v.x * v.x + v.y * v.y + v.z * v.z + v.w * v.w;
    float dw = 0.f;
    if (blockIdx.y == 0) {
        const float4 w = ((const float4*)wg)[tid];
        dw = v.x * w.x + v.y * w.y + v.z * w.z + v.w * w.w;
    }
#pragma unroll
    for (int o = 16; o > 0; o >>= 1) {
        ss += __shfl_down_sync(0xffffffffu, ss, o);
        dw += __shfl_down_sync(0xffffffffu, dw, o);
    }
    __shared__ float sss[4], sdw[4], bc;
    if ((tid & 31) == 0) { sss[tid >> 5] = ss; sdw[tid >> 5] = dw; }
    __syncthreads();
    if (tid == 0) {
        const float s = sss[0] + sss[1] + sss[2] + sss[3];
        const float scale = 1.0f / fmaxf(sqrtf(s), 1e-12f);
        bc = scale;
        if (blockIdx.y == 0) {
            const float d = sdw[0] + sdw[1] + sdw[2] + sdw[3];
            g_a[row] = d * scale * ATT_SCALE;
        }
    }
    __syncthreads();
    const float scale = bc;
    v.x *= scale; v.y *= scale; v.z *= scale; v.w *= scale;
    rp[tid] = v;
}

__global__ __launch_bounds__(256)
void softmax_kernel() {
    const int b = blockIdx.x;
    const int tid = threadIdx.x;
    __shared__ float sh[NTOK];
    __shared__ float red[8];
    __shared__ float stat[2];
    float m = -1e30f;
    for (int i = tid; i < NTOK; i += 256) {
        const float v = g_a[b * NTOK + i]; sh[i] = v; m = fmaxf(m, v);
    }
#pragma unroll
    for (int o = 16; o > 0; o >>= 1) m = fmaxf(m, __shfl_down_sync(0xffffffffu, m, o));
    if ((tid & 31) == 0) red[tid >> 5] = m;
    __syncthreads();
    if (tid == 0) {
        float mm = red[0];
        for (int i = 1; i < 8; i++) mm = fmaxf(mm, red[i]);
        stat[0] = mm;
    }
    __syncthreads();
    const float M = stat[0];
    float s = 0.f;
    for (int i = tid; i < NTOK; i += 256) {
        const float e = expf(sh[i] - M); sh[i] = e; s += e;
    }
#pragma unroll
    for (int o = 16; o > 0; o >>= 1) s += __shfl_down_sync(0xffffffffu, s, o);
    __syncthreads();                       // tid0 done reading red (max)
    if ((tid & 31) == 0) red[tid >> 5] = s;
    __syncthreads();
    if (tid == 0) {
        float t = 0.f;
        for (int i = 0; i < 8; i++) t += red[i];
        stat[1] = 1.0f / t;
    }
    __syncthreads();
    const float inv = stat[1];
    for (int i = tid; i < NTOK; i += 256) g_a[b * NTOK + i] = sh[i] * inv;
}

// deterministic split-K partial g: g_gp[split][b, d] = sum over token subset
__global__ __launch_bounds__(256)
void gsum_kernel() {
    const int b = blockIdx.x;
    const int d = threadIdx.x * 2;
    float ax = 0.f, ay = 0.f;
    for (int n = blockIdx.y; n < NTOK; n += NSPLIT) {
        const float w = g_a[b * NTOK + n];
        const float2 qv = *(const float2*)(g_q + ((size_t)(b * NTOK + n)) * DIM + d);
        ax += w * qv.x; ay += w * qv.y;
    }
    g_gp[(size_t)blockIdx.y * BATCH * DIM + b * DIM + d]     = ax;
    g_gp[(size_t)blockIdx.y * BATCH * DIM + b * DIM + d + 1] = ay;
}

__global__ __launch_bounds__(256)
void greduce_kernel() {
    const int i = blockIdx.x * 256 + threadIdx.x;   // < BATCH*DIM (exact)
    float s = 0.f;
#pragma unroll
    for (int p = 0; p < NSPLIT; p++) s += g_gp[(size_t)p * BATCH * DIM + i];
    g_g[i] = s;
}

__global__ __launch_bounds__(256)
void ymul_kernel() {
    const int idx = blockIdx.x * 256 + threadIdx.x;  // < M_VRT*128 (exact)
    const int m = idx >> 7, j = idx & 127;
    const int b = m / NVERT, t = m - b * NVERT;
    const float4 kv = ((const float4*)g_k)[((size_t)(b * NTOK + t)) * 128 + j];
    const float4 gv = ((const float4*)g_g)[b * 128 + j];
    ((float4*)g_y)[idx] = make_float4(kv.x * gv.x, kv.y * gv.y, kv.z * gv.z, kv.w * gv.w);
}

// ---------------------------------------------------------------------------

extern "C" void kernel_launch(void* const* d_in, const int* in_sizes, int n_in,
                              void* d_out, int out_size) {
    const float* verts   = (const float*)d_in[0];
    const float* img_f   = (const float*)d_in[1];
    const float* fc_w    = (const float*)d_in[2];
    const float* fc_b    = (const float*)d_in[3];
    const float* q_w     = (const float*)d_in[4];
    const float* q_b     = (const float*)d_in[5];
    const float* k_w     = (const float*)d_in[6];
    const float* k_b     = (const float*)d_in[7];
    const float* w_g     = (const float*)d_in[8];
    const float* proj_w  = (const float*)d_in[9];
    const float* proj_b  = (const float*)d_in[10];
    const float* final_w = (const float*)d_in[11];
    const float* final_b = (const float*)d_in[12];
    float* out = (float*)d_out;

    float *px, *pq, *pk, *py, *po1;
    cudaGetSymbolAddress((void**)&px,  g_x);
    cudaGetSymbolAddress((void**)&pq,  g_q);
    cudaGetSymbolAddress((void**)&pk,  g_k);
    cudaGetSymbolAddress((void**)&py,  g_y);
    cudaGetSymbolAddress((void**)&po1, g_o1);

    cudaFuncSetAttribute(gemm_tn_kernel,
                         cudaFuncAttributeMaxDynamicSharedMemorySize, GEMM_SMEM);

    const RMap direct    = {1 << 30, 0, 0};
    const RMap img_cmap  = {NIMG,  NTOK, NVERT};   // m -> (m/256)*1812 + m%256 + 1556
    const RMap vert_emap = {NVERT, NTOK, 0};       // m -> (m/1556)*1812 + m%1556

    copy_verts_kernel<<<(M_VRT * 128) / 256, 256>>>((const float4*)verts);
    gemm_tn_kernel<<<dim3(DIM / BN, M_IMG / BM), 256, GEMM_SMEM>>>(
        img_f, fc_w, fc_b, nullptr, px, IMGDIM, img_cmap, direct);
    gemm_tn_kernel<<<dim3(DIM / BN, M_ALL / BM), 256, GEMM_SMEM>>>(
        px, q_w, q_b, nullptr, pq, DIM, direct, direct);
    gemm_tn_kernel<<<dim3(DIM / BN, M_ALL / BM), 256, GEMM_SMEM>>>(
        px, k_w, k_b, nullptr, pk, DIM, direct, direct);
    norm_kernel<<<dim3(M_ALL, 2), 128>>>(w_g);
    softmax_kernel<<<BATCH, 256>>>();
    gsum_kernel<<<dim3(BATCH, NSPLIT), 256>>>();
    greduce_kernel<<<(BATCH * DIM) / 256, 256>>>();
    ymul_kernel<<<(M_VRT * 128) / 256, 256>>>();
    gemm_tn_kernel<<<dim3(DIM / BN, M_VRT / BM), 256, GEMM_SMEM>>>(
        py, proj_w, proj_b, pq, po1, DIM, direct, vert_emap);
    gemm_tn_kernel<<<dim3(DIM / BN, M_VRT / BM), 256, GEMM_SMEM>>>(
        po1, final_w, final_b, verts, out, DIM, direct, direct);
}

// round 6
// speedup vs baseline: 1.1630x; 1.1630x over previous
#include <cuda_runtime.h>
#include <cstdint>

// ---------------------------------------------------------------------------
// img_attn: B=32, Nv=1556, Ni=256, N=1812 tokens, D=512, IMG_D=2048
//
//  G1 gemm:     img_f @ fc_w^T + fc_b            -> g_xi  [B*Ni, D]
//  G2 gemm:     split(verts,g_xi) @ q_w^T + q_b  -> g_q   (A-row two-source)
//  G3 gemm:     split(verts,g_xi) @ k_w^T + k_b  -> g_k
//  K4 rowstat:  qs=1/||q||, ks=1/||k||, logits a=(q.w_g)*qs*SCALE (read-only)
//  K5 softmax:  per-batch over 1812 tokens (in g_a)
//  K6 gsum:     g = sum_n (a_n*qs_n) q_n   (deterministic split-K) + reduce
//  K7 ymul:     y = g[b] * k * ks          (vert rows only)
//  G4 gemm:     y @ proj_w^T + proj_b + qs*q  -> g_o1   (E with escale)
//  G5 gemm:     g_o1 @ final_w^T + final_b + verts -> out
//
// GEMM: 128x128x32 tiles, tf32 mma.sync m16n8k8 fed with RAW fp32 bits
// (HW truncates to tf32 -> no cvt instructions), cp.async double buffer,
// smem stride 36, 256 threads, 2 CTAs/SM.
// ---------------------------------------------------------------------------

#define BATCH 32
#define NVERT 1556
#define NIMG  256
#define NTOK  1812
#define DIM   512
#define IMGDIM 2048
#define M_ALL (BATCH * NTOK)    // 57984
#define M_VRT (BATCH * NVERT)   // 49792
#define M_IMG (BATCH * NIMG)    // 8192
#define ATT_SCALE 0.08838834764831845f   // (512/4)^-0.5
#define NSPLIT 16

__device__ __align__(256) float g_xi[(size_t)M_IMG * DIM];
__device__ __align__(256) float g_q [(size_t)M_ALL * DIM];
__device__ __align__(256) float g_k [(size_t)M_ALL * DIM];
__device__ __align__(256) float g_y [(size_t)M_VRT * DIM];
__device__ __align__(256) float g_o1[(size_t)M_VRT * DIM];
__device__ __align__(256) float g_a [M_ALL];
__device__ __align__(256) float g_qs[M_ALL];
__device__ __align__(256) float g_ks[M_ALL];
__device__ __align__(256) float g_g [BATCH * DIM];
__device__ __align__(256) float g_gp[NSPLIT * BATCH * DIM];

struct RMap { int div, stride, off; };
__device__ __forceinline__ int rmap_apply(const RMap m, int r) {
    int q = r / m.div;
    return q * m.stride + (r - q * m.div) + m.off;
}

__device__ __forceinline__ void mma_tf32(float* d, const uint32_t* a, const uint32_t* b) {
    asm volatile(
        "mma.sync.aligned.m16n8k8.row.col.f32.tf32.tf32.f32 "
        "{%0,%1,%2,%3},{%4,%5,%6,%7},{%8,%9},{%0,%1,%2,%3};"
        : "+f"(d[0]), "+f"(d[1]), "+f"(d[2]), "+f"(d[3])
        : "r"(a[0]), "r"(a[1]), "r"(a[2]), "r"(a[3]), "r"(b[0]), "r"(b[1]));
}

#define BM 128
#define BN 128
#define BKS 32
#define SSTR 36
#define GEMM_SMEM (2 * (BM + BN) * SSTR * (int)sizeof(float))  // 73728 B

// A1 == nullptr -> A rows read directly from A0 with leading dim K.
// A1 != nullptr -> token-split source: row r -> b=r/NTOK, t=r%NTOK;
//                  t <  NVERT: A0[b*NVERT+t]   (verts_f)
//                  t >= NVERT: A1[b*NIMG+t-NVERT] (img projection), K=DIM.
__global__ __launch_bounds__(256, 2)
void gemm_tn_kernel(const float* __restrict__ A0, const float* __restrict__ A1,
                    const float* __restrict__ Bw,
                    const float* __restrict__ bias,
                    const float* __restrict__ E, const float* __restrict__ escale,
                    float* __restrict__ C, int K, RMap cmap, RMap emap)
{
    extern __shared__ float smem[];
    float* As = smem;                       // [2][BM][SSTR]
    float* Bs = smem + 2 * BM * SSTR;       // [2][BN][SSTR]

    const int tid  = threadIdx.x;
    const int lane = tid & 31;
    const int warp = tid >> 5;
    const int wm   = warp >> 2;
    const int wn   = warp & 3;
    const long rowA0 = (long)blockIdx.y * BM;
    const long rowB0 = (long)blockIdx.x * BN;

    // per-thread A row base pointers for the 4 load rows (constant across k)
    const float* arow[4];
#pragma unroll
    for (int j = 0; j < 4; j++) {
        const int r = (tid + j * 256) >> 3;          // 0..127
        const long rr = rowA0 + r;
        if (A1) {
            const int b = (int)(rr / NTOK);
            const int t = (int)(rr - (long)b * NTOK);
            arow[j] = (t < NVERT) ? A0 + ((size_t)b * NVERT + t) * DIM
                                  : A1 + ((size_t)b * NIMG + (t - NVERT)) * DIM;
        } else {
            arow[j] = A0 + rr * (long)K;
        }
    }

    float acc[4][4][4];
#pragma unroll
    for (int mt = 0; mt < 4; mt++)
#pragma unroll
        for (int nt = 0; nt < 4; nt++)
#pragma unroll
            for (int i = 0; i < 4; i++) acc[mt][nt][i] = 0.f;

    auto load_tiles = [&](int buf, int kt) {
        const int k0 = kt * BKS;
#pragma unroll
        for (int j = 0; j < 4; j++) {
            const int idx = tid + j * 256;
            const int r = idx >> 3;
            const int c = (idx & 7) << 2;
            {
                const float* gp = arow[j] + k0 + c;
                uint32_t sp = (uint32_t)__cvta_generic_to_shared(
                    As + buf * BM * SSTR + r * SSTR + c);
                asm volatile("cp.async.cg.shared.global [%0], [%1], 16;"
                             :: "r"(sp), "l"(gp));
            }
            {
                const float* gp = Bw + (rowB0 + r) * (long)K + k0 + c;
                uint32_t sp = (uint32_t)__cvta_generic_to_shared(
                    Bs + buf * BN * SSTR + r * SSTR + c);
                asm volatile("cp.async.cg.shared.global [%0], [%1], 16;"
                             :: "r"(sp), "l"(gp));
            }
        }
        asm volatile("cp.async.commit_group;" ::: "memory");
    };

    const int T = K / BKS;
    load_tiles(0, 0);
    int buf = 0;

    for (int t = 0; t < T; t++) {
        asm volatile("cp.async.wait_group 0;" ::: "memory");
        __syncthreads();
        if (t + 1 < T) load_tiles(buf ^ 1, t + 1);

        const uint32_t* Ab = (const uint32_t*)(As + buf * BM * SSTR);
        const uint32_t* Bb = (const uint32_t*)(Bs + buf * BN * SSTR);
#pragma unroll
        for (int ks = 0; ks < 4; ks++) {
            const int kc = ks * 8 + (lane & 3);
            uint32_t af[4][4], bf[4][2];
#pragma unroll
            for (int mt = 0; mt < 4; mt++) {
                const int r = wm * 64 + mt * 16 + (lane >> 2);
                af[mt][0] = Ab[r * SSTR + kc];          // raw fp32 bits: HW
                af[mt][1] = Ab[(r + 8) * SSTR + kc];    // truncates to tf32
                af[mt][2] = Ab[r * SSTR + kc + 4];
                af[mt][3] = Ab[(r + 8) * SSTR + kc + 4];
            }
#pragma unroll
            for (int nt = 0; nt < 4; nt++) {
                const int n = wn * 32 + nt * 8 + (lane >> 2);
                bf[nt][0] = Bb[n * SSTR + kc];
                bf[nt][1] = Bb[n * SSTR + kc + 4];
            }
#pragma unroll
            for (int mt = 0; mt < 4; mt++)
#pragma unroll
                for (int nt = 0; nt < 4; nt++)
                    mma_tf32(acc[mt][nt], af[mt], bf[nt]);
        }
        buf ^= 1;
    }

    // epilogue: + bias (+ escale*E), write via row maps
#pragma unroll
    for (int mt = 0; mt < 4; mt++) {
        const int gr0 = (int)rowA0 + wm * 64 + mt * 16 + (lane >> 2);
        const int gr1 = gr0 + 8;
        const int cr0 = rmap_apply(cmap, gr0);
        const int cr1 = rmap_apply(cmap, gr1);
        int er0 = 0, er1 = 0;
        float es0 = 1.f, es1 = 1.f;
        if (E) {
            er0 = rmap_apply(emap, gr0); er1 = rmap_apply(emap, gr1);
            if (escale) { es0 = escale[er0]; es1 = escale[er1]; }
        }
#pragma unroll
        for (int nt = 0; nt < 4; nt++) {
            const int gc = (int)rowB0 + wn * 32 + nt * 8 + ((lane & 3) << 1);
            const float2 bb = *(const float2*)(bias + gc);
            float2 v0 = make_float2(acc[mt][nt][0] + bb.x, acc[mt][nt][1] + bb.y);
            float2 v1 = make_float2(acc[mt][nt][2] + bb.x, acc[mt][nt][3] + bb.y);
            if (E) {
                const float2 e0 = *(const float2*)(E + (size_t)er0 * DIM + gc);
                const float2 e1 = *(const float2*)(E + (size_t)er1 * DIM + gc);
                v0.x += es0 * e0.x; v0.y += es0 * e0.y;
                v1.x += es1 * e1.x; v1.y += es1 * e1.y;
            }
            *(float2*)(C + (size_t)cr0 * DIM + gc) = v0;
            *(float2*)(C + (size_t)cr1 * DIM + gc) = v1;
        }
    }
}

// ---------------------------------------------------------------------------
// Elementwise / reduction kernels
// ---------------------------------------------------------------------------

// read-only row stats: g_qs = 1/||q||, g_ks = 1/||k||, g_a = (q.w_g)*qs*SCALE
__global__ __launch_bounds__(128)
void rowstat_kernel(const float* __restrict__ wg) {
    const int row = blockIdx.x;
    const int tid = threadIdx.x;
    const float4 qv = ((const float4*)(g_q + (size_t)row * DIM))[tid];
    const float4 kv = ((const float4*)(g_k + (size_t)row * DIM))[tid];
    const float4 w  = ((const float4*)wg)[tid];
    float sq = qv.x * qv.x + qv.y * qv.y + qv.z * qv.z + qv.w * qv.w;
    float dw = qv.x * w.x + qv.y * w.y + qv.z * w.z + qv.w * w.w;
    float sk = kv.x * kv.x + kv.y * kv.y + kv.z * kv.z + kv.w * kv.w;
#pragma unroll
    for (int o = 16; o > 0; o >>= 1) {
        sq += __shfl_down_sync(0xffffffffu, sq, o);
        dw += __shfl_down_sync(0xffffffffu, dw, o);
        sk += __shfl_down_sync(0xffffffffu, sk, o);
    }
    __shared__ float rq[4], rd[4], rk[4];
    if ((tid & 31) == 0) { rq[tid >> 5] = sq; rd[tid >> 5] = dw; rk[tid >> 5] = sk; }
    __syncthreads();
    if (tid == 0) {
        const float ssq = rq[0] + rq[1] + rq[2] + rq[3];
        const float ssk = rk[0] + rk[1] + rk[2] + rk[3];
        const float d   = rd[0] + rd[1] + rd[2] + rd[3];
        const float qs  = 1.0f / fmaxf(sqrtf(ssq), 1e-12f);
        g_qs[row] = qs;
        g_ks[row] = 1.0f / fmaxf(sqrtf(ssk), 1e-12f);
        g_a[row]  = d * qs * ATT_SCALE;
    }
}

__global__ __launch_bounds__(256)
void softmax_kernel() {
    const int b = blockIdx.x;
    const int tid = threadIdx.x;
    __shared__ float sh[NTOK];
    __shared__ float red[8];
    __shared__ float stat[2];
    float m = -1e30f;
    for (int i = tid; i < NTOK; i += 256) {
        const float v = g_a[b * NTOK + i]; sh[i] = v; m = fmaxf(m, v);
    }
#pragma unroll
    for (int o = 16; o > 0; o >>= 1) m = fmaxf(m, __shfl_down_sync(0xffffffffu, m, o));
    if ((tid & 31) == 0) red[tid >> 5] = m;
    __syncthreads();
    if (tid == 0) {
        float mm = red[0];
        for (int i = 1; i < 8; i++) mm = fmaxf(mm, red[i]);
        stat[0] = mm;
    }
    __syncthreads();
    const float M = stat[0];
    float s = 0.f;
    for (int i = tid; i < NTOK; i += 256) {
        const float e = expf(sh[i] - M); sh[i] = e; s += e;
    }
#pragma unroll
    for (int o = 16; o > 0; o >>= 1) s += __shfl_down_sync(0xffffffffu, s, o);
    __syncthreads();
    if ((tid & 31) == 0) red[tid >> 5] = s;
    __syncthreads();
    if (tid == 0) {
        float t = 0.f;
        for (int i = 0; i < 8; i++) t += red[i];
        stat[1] = 1.0f / t;
    }
    __syncthreads();
    const float inv = stat[1];
    for (int i = tid; i < NTOK; i += 256) g_a[b * NTOK + i] = sh[i] * inv;
}

// deterministic split-K partials of g = sum_n (a_n * qs_n) * q_n
__global__ __launch_bounds__(256)
void gsum_kernel() {
    const int b = blockIdx.x;
    const int d = threadIdx.x * 2;
    float ax = 0.f, ay = 0.f;
    for (int n = blockIdx.y; n < NTOK; n += NSPLIT) {
        const int row = b * NTOK + n;
        const float w = g_a[row] * g_qs[row];
        const float2 qv = *(const float2*)(g_q + (size_t)row * DIM + d);
        ax += w * qv.x; ay += w * qv.y;
    }
    g_gp[(size_t)blockIdx.y * BATCH * DIM + b * DIM + d]     = ax;
    g_gp[(size_t)blockIdx.y * BATCH * DIM + b * DIM + d + 1] = ay;
}

__global__ __launch_bounds__(256)
void greduce_kernel() {
    const int i = blockIdx.x * 256 + threadIdx.x;
    float s = 0.f;
#pragma unroll
    for (int p = 0; p < NSPLIT; p++) s += g_gp[(size_t)p * BATCH * DIM + i];
    g_g[i] = s;
}

// y = g[b] * k * ks   (vert rows only)
__global__ __launch_bounds__(256)
void ymul_kernel() {
    const int idx = blockIdx.x * 256 + threadIdx.x;   // < M_VRT*128 (exact)
    const int m = idx >> 7, j = idx & 127;
    const int b = m / NVERT, t = m - b * NVERT;
    const int row = b * NTOK + t;
    const float ks = g_ks[row];
    const float4 kv = ((const float4*)g_k)[(size_t)row * 128 + j];
    const float4 gv = ((const float4*)g_g)[b * 128 + j];
    ((float4*)g_y)[idx] = make_float4(kv.x * gv.x * ks, kv.y * gv.y * ks,
                                      kv.z * gv.z * ks, kv.w * gv.w * ks);
}

// ---------------------------------------------------------------------------

extern "C" void kernel_launch(void* const* d_in, const int* in_sizes, int n_in,
                              void* d_out, int out_size) {
    const float* verts   = (const float*)d_in[0];
    const float* img_f   = (const float*)d_in[1];
    const float* fc_w    = (const float*)d_in[2];
    const float* fc_b    = (const float*)d_in[3];
    const float* q_w     = (const float*)d_in[4];
    const float* q_b     = (const float*)d_in[5];
    const float* k_w     = (const float*)d_in[6];
    const float* k_b     = (const float*)d_in[7];
    const float* w_g     = (const float*)d_in[8];
    const float* proj_w  = (const float*)d_in[9];
    const float* proj_b  = (const float*)d_in[10];
    const float* final_w = (const float*)d_in[11];
    const float* final_b = (const float*)d_in[12];
    float* out = (float*)d_out;

    float *pxi, *pq, *pk, *py, *po1, *pqs;
    cudaGetSymbolAddress((void**)&pxi, g_xi);
    cudaGetSymbolAddress((void**)&pq,  g_q);
    cudaGetSymbolAddress((void**)&pk,  g_k);
    cudaGetSymbolAddress((void**)&py,  g_y);
    cudaGetSymbolAddress((void**)&po1, g_o1);
    cudaGetSymbolAddress((void**)&pqs, g_qs);

    cudaFuncSetAttribute(gemm_tn_kernel,
                         cudaFuncAttributeMaxDynamicSharedMemorySize, GEMM_SMEM);

    const RMap direct    = {1 << 30, 0, 0};
    const RMap vert_emap = {NVERT, NTOK, 0};   // vert-row -> all-token row

    // G1: img projection
    gemm_tn_kernel<<<dim3(DIM / BN, M_IMG / BM), 256, GEMM_SMEM>>>(
        img_f, nullptr, fc_w, fc_b, nullptr, nullptr, pxi, IMGDIM, direct, direct);
    // G2/G3: q, k from split(verts, img-proj)
    gemm_tn_kernel<<<dim3(DIM / BN, M_ALL / BM), 256, GEMM_SMEM>>>(
        verts, pxi, q_w, q_b, nullptr, nullptr, pq, DIM, direct, direct);
    gemm_tn_kernel<<<dim3(DIM / BN, M_ALL / BM), 256, GEMM_SMEM>>>(
        verts, pxi, k_w, k_b, nullptr, nullptr, pk, DIM, direct, direct);
    rowstat_kernel<<<M_ALL, 128>>>(w_g);
    softmax_kernel<<<BATCH, 256>>>();
    gsum_kernel<<<dim3(BATCH, NSPLIT), 256>>>();
    greduce_kernel<<<(BATCH * DIM) / 256, 256>>>();
    ymul_kernel<<<(M_VRT * 128) / 256, 256>>>();
    // G4: proj with fused  + qs*q  residual
    gemm_tn_kernel<<<dim3(DIM / BN, M_VRT / BM), 256, GEMM_SMEM>>>(
        py, nullptr, proj_w, proj_b, pq, pqs, po1, DIM, direct, vert_emap);
    // G5: final with fused + verts residual
    gemm_tn_kernel<<<dim3(DIM / BN, M_VRT / BM), 256, GEMM_SMEM>>>(
        po1, nullptr, final_w, final_b, verts, nullptr, out, DIM, direct, direct);
}